// round 5
// baseline (speedup 1.0000x reference)
#include <cuda_runtime.h>
#include <cuda_fp16.h>
#include <cstdint>

// ============================================================================
// INT4Linear on GB300 — tcgen05 cta_group::2 (2-CTA MMA), tile 256x512.
//   out[M,N] = x[M,K] @ W[N,K]^T + bias     M=8192 N=4096 K=4096
// k1: dequant int4 -> g_W fp16, SW128 blocks [N/512][K/64][4][128x64]
//     inner block idx = r*2 + j  (r = (n>>7)&1 CTA rank, j = (n>>8)&1 N-half)
// k2: x fp32 -> g_X fp16, SW128 blocks [M/128][K/64][128x64]
// k3: cluster(2) GEMM: CTA pair = M 256 rows; each CTA loads A 16KB + B 32KB
//     per K-chunk(64); leader issues cg2 MMAs (2 x N=256 per k-step) into
//     512-col TMEM; multicast commits drive empty/done on both CTAs.
// Rationale: R4 mainloop was LTS-delivery-bound (14.2 KB/cyc demand vs
// ~6.3 cap). cg2 doubles MACs per delivered byte -> 7.1 KB/cyc.
// ============================================================================

#if defined(__CUDA_ARCH_FEAT_SM103_ALL) || defined(__CUDA_ARCH_FEAT_SM100_ALL)
#define TC_PATH 1
#else
#define TC_PATH 0
#endif

#define KC_ELEMS 64
#define BLK_BYTES 16384
#define STAGES 4
#define STAGE_BYTES (3 * BLK_BYTES)   // A 16KB + B 32KB
#define SMEM_STAGE0 1024
#define SMEM_TOTAL_GEMM (SMEM_STAGE0 + STAGES * STAGE_BYTES)   // 197632

__device__ __half g_W[4096u * 4096u];   // 32 MB, tiled+swizzled
__device__ __half g_X[8192u * 4096u];   // 64 MB, tiled+swizzled

__host__ __device__ __forceinline__ uint32_t swz128(uint32_t o) {
    return o ^ ((o >> 3) & 0x70);
}
__device__ __forceinline__ uint32_t smem_u32(const void* p) {
    return (uint32_t)__cvta_generic_to_shared(p);
}

// ---------------------------------------------------------------------------
// sm_103a-only helpers
// ---------------------------------------------------------------------------
#if TC_PATH
__device__ __forceinline__ void mbar_init(uint32_t a, uint32_t cnt) {
    asm volatile("mbarrier.init.shared.b64 [%0], %1;" :: "r"(a), "r"(cnt) : "memory");
}
__device__ __forceinline__ void mbar_expect_tx(uint32_t a, uint32_t bytes) {
    asm volatile("mbarrier.arrive.expect_tx.shared.b64 _, [%0], %1;"
                 :: "r"(a), "r"(bytes) : "memory");
}
__device__ __forceinline__ void mbar_wait(uint32_t a, uint32_t parity) {
    uint32_t done;
    asm volatile(
        "{\n\t.reg .pred p;\n\t"
        "mbarrier.try_wait.parity.acquire.cta.shared::cta.b64 p, [%1], %2;\n\t"
        "selp.b32 %0, 1, 0, p;\n\t}"
        : "=r"(done) : "r"(a), "r"(parity) : "memory");
    if (!done) {
        asm volatile(
            "{\n\t.reg .pred P1;\n\t"
            "W0_%=:\n\t"
            "mbarrier.try_wait.parity.acquire.cta.shared::cta.b64 P1, [%0], %1, 0x989680;\n\t"
            "@P1 bra.uni W1_%=;\n\t"
            "bra.uni W0_%=;\n\t"
            "W1_%=:\n\t}"
            :: "r"(a), "r"(parity) : "memory");
    }
}
// cluster-scope acquire (consumer of peer-CTA data)
__device__ __forceinline__ void mbar_wait_cl(uint32_t a, uint32_t parity) {
    uint32_t done;
    asm volatile(
        "{\n\t.reg .pred p;\n\t"
        "mbarrier.try_wait.parity.acquire.cluster.shared::cta.b64 p, [%1], %2;\n\t"
        "selp.b32 %0, 1, 0, p;\n\t}"
        : "=r"(done) : "r"(a), "r"(parity) : "memory");
    if (!done) {
        asm volatile(
            "{\n\t.reg .pred P1;\n\t"
            "W0_%=:\n\t"
            "mbarrier.try_wait.parity.acquire.cluster.shared::cta.b64 P1, [%0], %1, 0x989680;\n\t"
            "@P1 bra.uni W1_%=;\n\t"
            "bra.uni W0_%=;\n\t"
            "W1_%=:\n\t}"
            :: "r"(a), "r"(parity) : "memory");
    }
}
__device__ __forceinline__ void mbar_arrive_peer(uint32_t local_addr, uint32_t rank) {
    asm volatile(
        "{\n\t.reg .b32 ra;\n\t"
        "mapa.shared::cluster.u32 ra, %0, %1;\n\t"
        "mbarrier.arrive.release.cluster.shared::cluster.b64 _, [ra];\n\t}"
        :: "r"(local_addr), "r"(rank) : "memory");
}
__device__ __forceinline__ void bulk_g2s(uint32_t dst, const void* src,
                                         uint32_t bytes, uint32_t mbar) {
    asm volatile(
        "cp.async.bulk.shared::cluster.global.mbarrier::complete_tx::bytes "
        "[%0], [%1], %2, [%3];"
        :: "r"(dst), "l"(src), "r"(bytes), "r"(mbar) : "memory");
}
__device__ __forceinline__ void tmem_alloc_cg2(uint32_t smem_slot, uint32_t ncols) {
    asm volatile("tcgen05.alloc.cta_group::2.sync.aligned.shared::cta.b32 [%0], %1;"
                 :: "r"(smem_slot), "r"(ncols) : "memory");
}
__device__ __forceinline__ void tmem_relinquish_cg2() {
    asm volatile("tcgen05.relinquish_alloc_permit.cta_group::2.sync.aligned;");
}
__device__ __forceinline__ void tmem_dealloc_cg2(uint32_t base, uint32_t ncols) {
    asm volatile("tcgen05.dealloc.cta_group::2.sync.aligned.b32 %0, %1;"
                 :: "r"(base), "r"(ncols));
}
__device__ __forceinline__ void mma_f16_ss_cg2(uint32_t d_tmem, uint64_t a_desc,
                                               uint64_t b_desc, uint32_t idesc,
                                               uint32_t enable) {
    asm volatile(
        "{\n\t.reg .pred p;\n\t"
        "setp.ne.u32 p, %5, 0;\n\t"
        "tcgen05.mma.cta_group::2.kind::f16 [%0], %1, %2, %3, "
        "{%4, %4, %4, %4, %4, %4, %4, %4}, p;\n\t}"
        :: "r"(d_tmem), "l"(a_desc), "l"(b_desc), "r"(idesc), "r"(0u), "r"(enable)
        : "memory");
}
__device__ __forceinline__ void tc_commit_mc_cg2(uint32_t mbar, uint16_t mask) {
    asm volatile(
        "tcgen05.commit.cta_group::2.mbarrier::arrive::one.shared::cluster"
        ".multicast::cluster.b64 [%0], %1;"
        :: "r"(mbar), "h"(mask) : "memory");
}
__device__ __forceinline__ void tc_fence_after() {
    asm volatile("tcgen05.fence::after_thread_sync;" ::: "memory");
}
__device__ __forceinline__ void ldtm_x32(uint32_t* r, uint32_t addr) {
    asm volatile(
        "tcgen05.ld.sync.aligned.32x32b.x32.b32 "
        "{%0,%1,%2,%3,%4,%5,%6,%7,%8,%9,%10,%11,%12,%13,%14,%15,"
        "%16,%17,%18,%19,%20,%21,%22,%23,%24,%25,%26,%27,%28,%29,%30,%31}, [%32];"
        : "=r"(r[0]), "=r"(r[1]), "=r"(r[2]), "=r"(r[3]),
          "=r"(r[4]), "=r"(r[5]), "=r"(r[6]), "=r"(r[7]),
          "=r"(r[8]), "=r"(r[9]), "=r"(r[10]), "=r"(r[11]),
          "=r"(r[12]), "=r"(r[13]), "=r"(r[14]), "=r"(r[15]),
          "=r"(r[16]), "=r"(r[17]), "=r"(r[18]), "=r"(r[19]),
          "=r"(r[20]), "=r"(r[21]), "=r"(r[22]), "=r"(r[23]),
          "=r"(r[24]), "=r"(r[25]), "=r"(r[26]), "=r"(r[27]),
          "=r"(r[28]), "=r"(r[29]), "=r"(r[30]), "=r"(r[31])
        : "r"(addr));
}
__device__ __forceinline__ void tc_wait_ld() {
    asm volatile("tcgen05.wait::ld.sync.aligned;" ::: "memory");
}
__device__ __forceinline__ uint32_t cl_rank() {
    uint32_t r;
    asm("mov.u32 %0, %%cluster_ctarank;" : "=r"(r));
    return r;
}
#define CLUSTER_SYNC_() do { \
    asm volatile("barrier.cluster.arrive.aligned;" ::: "memory"); \
    asm volatile("barrier.cluster.wait.aligned;" ::: "memory"); \
} while (0)
// SW128 K-major SMEM descriptor (version=1, LBO=1, SBO=64)
__device__ __forceinline__ uint64_t make_desc(uint32_t smem_addr) {
    const uint64_t base =
        (uint64_t(2) << 61) | (uint64_t(1) << 46) | (uint64_t(64) << 32) | (uint64_t(1) << 16);
    return base | ((uint64_t)(smem_addr >> 4) & 0x3FFF);
}
// idesc cg2: dtype F32 (1<<4), fp16 a/b (0), N=256 (32<<17), M=256 (16<<24)
#define IDESC_CG2 0x10400010u
#endif  // TC_PATH

// ---------------------------------------------------------------------------
// k1: dequant int4 -> g_W blocks [N/512][K/64][4][16KB], inner = r*2 + j
// ---------------------------------------------------------------------------
__global__ void dequant_kernel(const int* __restrict__ packed,
                               const float* __restrict__ scale_p,
                               int total_bytes, int K) {
    int t = blockIdx.x * blockDim.x + threadIdx.x;
    if (t * 4 >= total_bytes) return;
    const float s = __ldg(scale_p);
    const int K2 = K >> 1;
    const int KC = K / KC_ELEMS;
    const int4 v = reinterpret_cast<const int4*>(packed)[t];

    int n  = (t * 4) / K2;
    int k0 = ((t * 4) % K2) * 2;     // multiple of 8

    __half out[8];
    const int b[4] = {v.x, v.y, v.z, v.w};
#pragma unroll
    for (int j = 0; j < 4; ++j) {
        int hi = b[j] >> 4;
        int lo = ((b[j] & 15) ^ 8) - 8;
        out[2 * j]     = __float2half_rn((float)hi * s);
        out[2 * j + 1] = __float2half_rn((float)lo * s);
    }

    int n512 = n >> 9;
    int jh   = (n >> 8) & 1;         // N-half within 512 tile
    int rr   = (n >> 7) & 1;         // CTA rank owning this 128-row block
    int row  = n & 127;
    int kc   = k0 >> 6;
    int c    = k0 & 63;
    size_t blk = ((size_t)n512 * KC + kc) * 4 + rr * 2 + jh;
    size_t off = blk * BLK_BYTES + swz128((uint32_t)(row * 128 + c * 2));
    *reinterpret_cast<uint4*>(reinterpret_cast<char*>(g_W) + off) =
        *reinterpret_cast<const uint4*>(out);
}

// ---------------------------------------------------------------------------
// k2: x fp32 -> g_X blocks [M/128][K/64][16KB]
// ---------------------------------------------------------------------------
__global__ void convert_x_kernel(const float* __restrict__ x, int total, int K) {
    int t = blockIdx.x * blockDim.x + threadIdx.x;
    if (t * 8 >= total) return;
    const int KC = K / KC_ELEMS;
    float4 a = reinterpret_cast<const float4*>(x)[t * 2];
    float4 c4 = reinterpret_cast<const float4*>(x)[t * 2 + 1];
    __half out[8];
    out[0] = __float2half_rn(a.x);  out[1] = __float2half_rn(a.y);
    out[2] = __float2half_rn(a.z);  out[3] = __float2half_rn(a.w);
    out[4] = __float2half_rn(c4.x); out[5] = __float2half_rn(c4.y);
    out[6] = __float2half_rn(c4.z); out[7] = __float2half_rn(c4.w);

    int m  = (t * 8) / K;
    int k0 = (t * 8) % K;
    int mb = m >> 7;
    int r  = m & 127;
    int kc = k0 >> 6;
    int c  = k0 & 63;
    size_t blk = (size_t)mb * KC + kc;
    size_t off = blk * BLK_BYTES + swz128((uint32_t)(r * 128 + c * 2));
    *reinterpret_cast<uint4*>(reinterpret_cast<char*>(g_X) + off) =
        *reinterpret_cast<const uint4*>(out);
}

// ---------------------------------------------------------------------------
// k3: GEMM. grid = (M/256 * 2, N/512), cluster (2,1,1), 128 threads/CTA.
// smem: full[4]@0, empty[4]@32, peer_full[4]@64, done@96, tmem slot@112,
//       stages @1024 (A 16KB | B 32KB each).
// ---------------------------------------------------------------------------
__global__ __launch_bounds__(128, 1) __cluster_dims__(2, 1, 1)
void gemm_kernel(const float* __restrict__ bias,
                 float* __restrict__ Out,
                 int M, int N, int K) {
    extern __shared__ char smem[];
    const uint32_t sbase = smem_u32(smem);
    const int tid  = threadIdx.x;
    const int wid  = tid >> 5;
    const int lane = tid & 31;

    const int KC   = K / KC_ELEMS;               // 64 chunks
    const int pair = blockIdx.x >> 1;            // M/256 tile
    const int nb   = blockIdx.y;                 // N/512 tile

#if TC_PATH
    const uint32_t rank  = cl_rank();            // 0 = leader
    const uint32_t full0 = sbase;
    const uint32_t empty0 = sbase + 32;
    const uint32_t peer0  = sbase + 64;
    const uint32_t doneb  = sbase + 96;
    const uint32_t tslot  = sbase + 112;

    if (tid == 0) {
#pragma unroll
        for (int s = 0; s < STAGES; ++s) {
            mbar_init(full0 + s * 8, 1);
            mbar_init(empty0 + s * 8, 1);
            mbar_init(peer0 + s * 8, 1);
        }
        mbar_init(doneb, 1);
    }
    __syncthreads();

    if (wid == 0) {
        tmem_alloc_cg2(tslot, 512);
        tmem_relinquish_cg2();
    }
    __syncthreads();
    uint32_t tmem_base;
    asm volatile("ld.shared.b32 %0, [%1];" : "=r"(tmem_base) : "r"(tslot));

    // barriers live in both CTAs before any cross-CTA arrive/commit
    CLUSTER_SYNC_();

    // A: this CTA's 128 M-rows (mb = pair*2 + rank)
    const char* Asrc = reinterpret_cast<const char*>(g_X) +
                       ((size_t)(pair * 2 + rank) * KC) * BLK_BYTES;
    // B: this CTA's two 128-row blocks (r = rank, j = 0,1) -> contiguous 32KB
    const char* Bsrc = reinterpret_cast<const char*>(g_W) +
                       ((size_t)nb * KC * 4 + rank * 2) * BLK_BYTES;

    // ---- producer: thread 0 of each CTA ----
    if (tid == 0) {
        int s = 0, phase = 1;
        for (int i = 0; i < KC; ++i) {
            mbar_wait(empty0 + s * 8, phase);
            const uint32_t fb = full0 + s * 8;
            mbar_expect_tx(fb, STAGE_BYTES);
            const uint32_t stg = sbase + SMEM_STAGE0 + s * STAGE_BYTES;
            bulk_g2s(stg,             Asrc + (size_t)i * BLK_BYTES,     BLK_BYTES,     fb);
            bulk_g2s(stg + BLK_BYTES, Bsrc + (size_t)i * 4 * BLK_BYTES, 2 * BLK_BYTES, fb);
            if (++s == STAGES) { s = 0; phase ^= 1; }
        }
    }

    // ---- relay (rank 1, thread 64): local full -> leader's peer_full ----
    if (rank == 1 && tid == 64) {
        int s = 0, phase = 0;
        for (int i = 0; i < KC; ++i) {
            mbar_wait(full0 + s * 8, phase);
            mbar_arrive_peer(peer0 + s * 8, 0);
            if (++s == STAGES) { s = 0; phase ^= 1; }
        }
    }

    // ---- MMA issuer (rank 0, thread 32) ----
    if (rank == 0 && tid == 32) {
        int s = 0, phase = 0;
        for (int i = 0; i < KC; ++i) {
            mbar_wait(full0 + s * 8, phase);        // local stage full
            mbar_wait_cl(peer0 + s * 8, phase);     // peer stage full
            const uint32_t stg = sbase + SMEM_STAGE0 + s * STAGE_BYTES;
            uint64_t ad = make_desc(stg);
            uint64_t bd = make_desc(stg + BLK_BYTES);
#pragma unroll
            for (int ks = 0; ks < 4; ++ks) {
#pragma unroll
                for (int j = 0; j < 2; ++j) {
                    mma_f16_ss_cg2(tmem_base + j * 256,
                                   ad + ks * 2,
                                   bd + j * (BLK_BYTES / 16) + ks * 2,
                                   IDESC_CG2,
                                   (i > 0 || ks > 0) ? 1u : 0u);
                }
            }
            tc_commit_mc_cg2(empty0 + s * 8, 0x3);  // free stage s on BOTH CTAs
            if (++s == STAGES) { s = 0; phase ^= 1; }
        }
        tc_commit_mc_cg2(doneb, 0x3);
    }

    // ---- epilogue: 4 warps per CTA, CTA owns 128 rows x 512 cols ----
    mbar_wait(doneb, 0);
    tc_fence_after();

    const int row = pair * 256 + (int)rank * 128 + wid * 32 + lane;
    float* orow = Out + (size_t)row * N + nb * 512;
    const float* brow = bias + nb * 512;

#pragma unroll
    for (int cb = 0; cb < 16; ++cb) {
        uint32_t r32[32];
        ldtm_x32(r32, tmem_base + cb * 32);
        tc_wait_ld();
        float o[32];
#pragma unroll
        for (int c = 0; c < 32; ++c) {
            __half h  = __float2half_rn(__uint_as_float(r32[c]));
            __half hb = __float2half_rn(__ldg(brow + cb * 32 + c));
            o[c] = __half2float(__hadd(h, hb));
        }
#pragma unroll
        for (int q = 0; q < 8; ++q) {
            reinterpret_cast<float4*>(orow + cb * 32)[q] =
                make_float4(o[4 * q], o[4 * q + 1], o[4 * q + 2], o[4 * q + 3]);
        }
    }

    __syncthreads();
    if (wid == 0) tmem_dealloc_cg2(tmem_base, 512);
    CLUSTER_SYNC_();

#else
    // =============== compile-only fallback (never selected on GB300) =======
    // Naive but correct: each thread computes one of the CTA's 128 rows.
    const int rank = blockIdx.x & 1;
    if (tid < 128) {
        const int m = pair * 256 + rank * 128 + tid;
        for (int c = 0; c < 512; ++c) {
            const int n = nb * 512 + c;
            float acc = 0.0f;
            for (int k = 0; k < K; ++k) {
                size_t ablk = (size_t)(m >> 7) * KC + (k >> 6);
                const __half* ae = reinterpret_cast<const __half*>(
                    reinterpret_cast<const char*>(g_X) + ablk * BLK_BYTES +
                    swz128((uint32_t)((m & 127) * 128 + (k & 63) * 2)));
                size_t bblk = ((size_t)(n >> 9) * KC + (k >> 6)) * 4 +
                              (((n >> 7) & 1) * 2) + ((n >> 8) & 1);
                const __half* be = reinterpret_cast<const __half*>(
                    reinterpret_cast<const char*>(g_W) + bblk * BLK_BYTES +
                    swz128((uint32_t)((n & 127) * 128 + (k & 63) * 2)));
                acc += __half2float(*ae) * __half2float(*be);
            }
            __half h = __hadd(__float2half_rn(acc), __float2half_rn(__ldg(bias + n)));
            Out[(size_t)m * N + n] = __half2float(h);
        }
    }
#endif
}

// ---------------------------------------------------------------------------
extern "C" void kernel_launch(void* const* d_in, const int* in_sizes, int n_in,
                              void* d_out, int out_size) {
    const float* x     = (const float*)d_in[0];
    const int*   wq    = (const int*)d_in[1];
    const float* scale = (const float*)d_in[2];
    const float* bias  = (const float*)d_in[3];
    float*       out   = (float*)d_out;

    const int O = in_sizes[3];                    // 4096
    const int K = (in_sizes[1] / O) * 2;          // 4096
    const int M = in_sizes[0] / K;                // 8192
    const int N = O;

    const int nbytes = in_sizes[1];
    dequant_kernel<<<(nbytes / 4 + 255) / 256, 256>>>(wq, scale, nbytes, K);

    const int nx = in_sizes[0];
    convert_x_kernel<<<(nx / 8 + 255) / 256, 256>>>(x, nx, K);

    cudaFuncSetAttribute(gemm_kernel,
                         cudaFuncAttributeMaxDynamicSharedMemorySize,
                         SMEM_TOTAL_GEMM);
    dim3 grid((M / 256) * 2, N / 512);
    gemm_kernel<<<grid, 128, SMEM_TOTAL_GEMM>>>(bias, out, M, N, K);
}

// round 7
// speedup vs baseline: 1.0565x; 1.0565x over previous
#include <cuda_runtime.h>
#include <cuda_fp16.h>
#include <cstdint>

// ============================================================================
// INT4Linear on GB300 — tcgen05 cg1 128x256 tiles + cluster-2 B multicast.
//   out[M,N] = x[M,K] @ W[N,K]^T + bias     M=8192 N=4096 K=4096
// k1: dequant int4 -> g_W fp16, SW128 blocks [N/256][K/64][2][128x64]
// k2: x fp32 -> g_X fp16, SW128 blocks [M/128][K/64][128x64]
// k3: cluster(2,1,1) over grid.x (M): pair CTAs share the SAME N-tile's B.
//     Each CTA bulk-loads A (16KB unicast) + ONE 16KB half of B multicast to
//     both CTAs (R6 bug: half was 8KB -> expect_tx never satisfied -> hang).
//     MMAs are cg1, fully local. empty[s] count=2, freed by both CTAs'
//     tcgen05.commit multicast.
// ============================================================================

#if defined(__CUDA_ARCH_FEAT_SM103_ALL) || defined(__CUDA_ARCH_FEAT_SM100_ALL)
#define TC_PATH 1
#else
#define TC_PATH 0
#endif

#define KC_ELEMS 64
#define BLK_BYTES 16384
#define HALF_BLK 16384                // half of the 32KB B tile (R6 had 8192: BUG)
#define STAGES 4
#define STAGE_BYTES (3 * BLK_BYTES)   // A 16KB + B 32KB
#define SMEM_STAGE0 1024
#define SMEM_TOTAL_GEMM (SMEM_STAGE0 + STAGES * STAGE_BYTES)   // 197632

__device__ __half g_W[4096u * 4096u];   // 32 MB, tiled+swizzled
__device__ __half g_X[8192u * 4096u];   // 64 MB, tiled+swizzled

__host__ __device__ __forceinline__ uint32_t swz128(uint32_t o) {
    return o ^ ((o >> 3) & 0x70);
}
__device__ __forceinline__ uint32_t smem_u32(const void* p) {
    return (uint32_t)__cvta_generic_to_shared(p);
}

// ---------------------------------------------------------------------------
// sm_103a-only helpers
// ---------------------------------------------------------------------------
#if TC_PATH
__device__ __forceinline__ void mbar_init(uint32_t a, uint32_t cnt) {
    asm volatile("mbarrier.init.shared.b64 [%0], %1;" :: "r"(a), "r"(cnt) : "memory");
}
__device__ __forceinline__ void mbar_expect_tx(uint32_t a, uint32_t bytes) {
    asm volatile("mbarrier.arrive.expect_tx.shared.b64 _, [%0], %1;"
                 :: "r"(a), "r"(bytes) : "memory");
}
__device__ __forceinline__ void mbar_wait(uint32_t a, uint32_t parity) {
    uint32_t done;
    asm volatile(
        "{\n\t.reg .pred p;\n\t"
        "mbarrier.try_wait.parity.acquire.cta.shared::cta.b64 p, [%1], %2;\n\t"
        "selp.b32 %0, 1, 0, p;\n\t}"
        : "=r"(done) : "r"(a), "r"(parity) : "memory");
    if (!done) {
        asm volatile(
            "{\n\t.reg .pred P1;\n\t"
            "W0_%=:\n\t"
            "mbarrier.try_wait.parity.acquire.cta.shared::cta.b64 P1, [%0], %1, 0x989680;\n\t"
            "@P1 bra.uni W1_%=;\n\t"
            "bra.uni W0_%=;\n\t"
            "W1_%=:\n\t}"
            :: "r"(a), "r"(parity) : "memory");
    }
}
__device__ __forceinline__ void bulk_g2s(uint32_t dst, const void* src,
                                         uint32_t bytes, uint32_t mbar) {
    asm volatile(
        "cp.async.bulk.shared::cluster.global.mbarrier::complete_tx::bytes "
        "[%0], [%1], %2, [%3];"
        :: "r"(dst), "l"(src), "r"(bytes), "r"(mbar) : "memory");
}
__device__ __forceinline__ void bulk_g2s_mc(uint32_t dst, const void* src,
                                            uint32_t bytes, uint32_t mbar,
                                            uint16_t mask) {
    asm volatile(
        "cp.async.bulk.shared::cluster.global.mbarrier::complete_tx::bytes"
        ".multicast::cluster [%0], [%1], %2, [%3], %4;"
        :: "r"(dst), "l"(src), "r"(bytes), "r"(mbar), "h"(mask) : "memory");
}
__device__ __forceinline__ void tmem_alloc(uint32_t smem_slot, uint32_t ncols) {
    asm volatile("tcgen05.alloc.cta_group::1.sync.aligned.shared::cta.b32 [%0], %1;"
                 :: "r"(smem_slot), "r"(ncols) : "memory");
}
__device__ __forceinline__ void tmem_relinquish() {
    asm volatile("tcgen05.relinquish_alloc_permit.cta_group::1.sync.aligned;");
}
__device__ __forceinline__ void tmem_dealloc(uint32_t base, uint32_t ncols) {
    asm volatile("tcgen05.dealloc.cta_group::1.sync.aligned.b32 %0, %1;"
                 :: "r"(base), "r"(ncols));
}
__device__ __forceinline__ void mma_f16_ss(uint32_t d_tmem, uint64_t a_desc,
                                           uint64_t b_desc, uint32_t idesc,
                                           uint32_t enable) {
    asm volatile(
        "{\n\t.reg .pred p;\n\t"
        "setp.ne.u32 p, %5, 0;\n\t"
        "tcgen05.mma.cta_group::1.kind::f16 [%0], %1, %2, %3, {%4, %4, %4, %4}, p;\n\t}"
        :: "r"(d_tmem), "l"(a_desc), "l"(b_desc), "r"(idesc), "r"(0u), "r"(enable)
        : "memory");
}
__device__ __forceinline__ void tc_commit(uint32_t mbar) {
    asm volatile(
        "tcgen05.commit.cta_group::1.mbarrier::arrive::one.shared::cluster.b64 [%0];"
        :: "r"(mbar) : "memory");
}
__device__ __forceinline__ void tc_commit_mc(uint32_t mbar, uint16_t mask) {
    asm volatile(
        "tcgen05.commit.cta_group::1.mbarrier::arrive::one.shared::cluster"
        ".multicast::cluster.b64 [%0], %1;"
        :: "r"(mbar), "h"(mask) : "memory");
}
__device__ __forceinline__ void tc_fence_after() {
    asm volatile("tcgen05.fence::after_thread_sync;" ::: "memory");
}
__device__ __forceinline__ void ldtm_x32(uint32_t* r, uint32_t addr) {
    asm volatile(
        "tcgen05.ld.sync.aligned.32x32b.x32.b32 "
        "{%0,%1,%2,%3,%4,%5,%6,%7,%8,%9,%10,%11,%12,%13,%14,%15,"
        "%16,%17,%18,%19,%20,%21,%22,%23,%24,%25,%26,%27,%28,%29,%30,%31}, [%32];"
        : "=r"(r[0]), "=r"(r[1]), "=r"(r[2]), "=r"(r[3]),
          "=r"(r[4]), "=r"(r[5]), "=r"(r[6]), "=r"(r[7]),
          "=r"(r[8]), "=r"(r[9]), "=r"(r[10]), "=r"(r[11]),
          "=r"(r[12]), "=r"(r[13]), "=r"(r[14]), "=r"(r[15]),
          "=r"(r[16]), "=r"(r[17]), "=r"(r[18]), "=r"(r[19]),
          "=r"(r[20]), "=r"(r[21]), "=r"(r[22]), "=r"(r[23]),
          "=r"(r[24]), "=r"(r[25]), "=r"(r[26]), "=r"(r[27]),
          "=r"(r[28]), "=r"(r[29]), "=r"(r[30]), "=r"(r[31])
        : "r"(addr));
}
__device__ __forceinline__ void tc_wait_ld() {
    asm volatile("tcgen05.wait::ld.sync.aligned;" ::: "memory");
}
__device__ __forceinline__ uint32_t cl_rank() {
    uint32_t r;
    asm("mov.u32 %0, %%cluster_ctarank;" : "=r"(r));
    return r;
}
#define CLUSTER_SYNC_() do { \
    asm volatile("barrier.cluster.arrive.aligned;" ::: "memory"); \
    asm volatile("barrier.cluster.wait.aligned;" ::: "memory"); \
} while (0)
// SW128 K-major SMEM descriptor (version=1, LBO=1, SBO=64)
__device__ __forceinline__ uint64_t make_desc(uint32_t smem_addr) {
    const uint64_t base =
        (uint64_t(2) << 61) | (uint64_t(1) << 46) | (uint64_t(64) << 32) | (uint64_t(1) << 16);
    return base | ((uint64_t)(smem_addr >> 4) & 0x3FFF);
}
// idesc cg1: dtype F32 (1<<4), fp16 a/b, N=256 (32<<17), M=128 (8<<24)
#define IDESC 0x8400010u
#endif  // TC_PATH

// ---------------------------------------------------------------------------
// k1: dequant int4 -> g_W blocks [N/256][K/64][2][16KB]
// ---------------------------------------------------------------------------
__global__ void dequant_kernel(const int* __restrict__ packed,
                               const float* __restrict__ scale_p,
                               int total_bytes, int K) {
    int t = blockIdx.x * blockDim.x + threadIdx.x;
    if (t * 4 >= total_bytes) return;
    const float s = __ldg(scale_p);
    const int K2 = K >> 1;
    const int KC = K / KC_ELEMS;
    const int4 v = reinterpret_cast<const int4*>(packed)[t];

    int n  = (t * 4) / K2;
    int k0 = ((t * 4) % K2) * 2;

    __half out[8];
    const int b[4] = {v.x, v.y, v.z, v.w};
#pragma unroll
    for (int j = 0; j < 4; ++j) {
        int hi = b[j] >> 4;
        int lo = ((b[j] & 15) ^ 8) - 8;
        out[2 * j]     = __float2half_rn((float)hi * s);
        out[2 * j + 1] = __float2half_rn((float)lo * s);
    }

    int n2   = n >> 8;
    int half = (n >> 7) & 1;
    int r    = n & 127;
    int kc   = k0 >> 6;
    int c    = k0 & 63;
    size_t blk = ((size_t)n2 * KC + kc) * 2 + half;
    size_t off = blk * BLK_BYTES + swz128((uint32_t)(r * 128 + c * 2));
    *reinterpret_cast<uint4*>(reinterpret_cast<char*>(g_W) + off) =
        *reinterpret_cast<const uint4*>(out);
}

// ---------------------------------------------------------------------------
// k2: x fp32 -> g_X blocks [M/128][K/64][16KB]
// ---------------------------------------------------------------------------
__global__ void convert_x_kernel(const float* __restrict__ x, int total, int K) {
    int t = blockIdx.x * blockDim.x + threadIdx.x;
    if (t * 8 >= total) return;
    const int KC = K / KC_ELEMS;
    float4 a = reinterpret_cast<const float4*>(x)[t * 2];
    float4 c4 = reinterpret_cast<const float4*>(x)[t * 2 + 1];
    __half out[8];
    out[0] = __float2half_rn(a.x);  out[1] = __float2half_rn(a.y);
    out[2] = __float2half_rn(a.z);  out[3] = __float2half_rn(a.w);
    out[4] = __float2half_rn(c4.x); out[5] = __float2half_rn(c4.y);
    out[6] = __float2half_rn(c4.z); out[7] = __float2half_rn(c4.w);

    int m  = (t * 8) / K;
    int k0 = (t * 8) % K;
    int mb = m >> 7;
    int r  = m & 127;
    int kc = k0 >> 6;
    int c  = k0 & 63;
    size_t blk = (size_t)mb * KC + kc;
    size_t off = blk * BLK_BYTES + swz128((uint32_t)(r * 128 + c * 2));
    *reinterpret_cast<uint4*>(reinterpret_cast<char*>(g_X) + off) =
        *reinterpret_cast<const uint4*>(out);
}

// ---------------------------------------------------------------------------
// k3: GEMM. grid = (M/128, N/256), cluster (2,1,1) along M. 256 threads.
// smem: full[4]@0, empty[4]@32, done@64, tmem slot@96, stages @1024.
// ---------------------------------------------------------------------------
__global__ __launch_bounds__(256, 1)
#if TC_PATH
__cluster_dims__(2, 1, 1)
#endif
void gemm_kernel(const float* __restrict__ bias,
                 float* __restrict__ Out,
                 int M, int N, int K) {
    extern __shared__ char smem[];
    const uint32_t sbase = smem_u32(smem);
    const int tid  = threadIdx.x;
    const int wid  = tid >> 5;
    const int lane = tid & 31;

    const int KC  = K / KC_ELEMS;                // 64 chunks
    const int mb  = blockIdx.x;                  // M/128 tile
    const int nb2 = blockIdx.y;                  // N/256 tile

    const char* Asrc = reinterpret_cast<const char*>(g_X) +
                       (size_t)mb * KC * BLK_BYTES;
    const char* Bsrc = reinterpret_cast<const char*>(g_W) +
                       (size_t)nb2 * KC * 2 * BLK_BYTES;

#if TC_PATH
    const uint32_t rank = cl_rank();
    const uint32_t full0  = sbase;               // full[s]  : +0  + s*8
    const uint32_t empty0 = sbase + 32;          // empty[s] : +32 + s*8
    const uint32_t doneb  = sbase + 64;
    const uint32_t tslot  = sbase + 96;

    if (tid == 0) {
#pragma unroll
        for (int s = 0; s < STAGES; ++s) {
            mbar_init(full0 + s * 8, 1);
            mbar_init(empty0 + s * 8, 2);        // freed by BOTH consumers
        }
        mbar_init(doneb, 1);
    }
    __syncthreads();

    if (wid == 0) {
        tmem_alloc(tslot, 256);
        tmem_relinquish();
    }
    __syncthreads();
    uint32_t tmem_base;
    asm volatile("ld.shared.b32 %0, [%1];" : "=r"(tmem_base) : "r"(tslot));

    // both CTAs' barriers must be live before any multicast targets them
    CLUSTER_SYNC_();

    // ---- producer: thread 0 of each CTA ----
    // A: 16KB unicast (own M rows). B: own 16KB half, multicast to both CTAs.
    // full[s] tx per CTA: A 16KB + own-half mc 16KB + peer-half mc 16KB = 48KB.
    if (tid == 0) {
        const uint32_t boff = BLK_BYTES + rank * HALF_BLK;
        int s = 0, phase = 1;
        for (int i = 0; i < KC; ++i) {
            mbar_wait(empty0 + s * 8, phase);
            const uint32_t fb = full0 + s * 8;
            mbar_expect_tx(fb, STAGE_BYTES);
            const uint32_t stg = sbase + SMEM_STAGE0 + s * STAGE_BYTES;
            bulk_g2s(stg, Asrc + (size_t)i * BLK_BYTES, BLK_BYTES, fb);
            bulk_g2s_mc(stg + boff,
                        Bsrc + (size_t)i * 2 * BLK_BYTES + rank * HALF_BLK,
                        HALF_BLK, fb, 0x3);
            if (++s == STAGES) { s = 0; phase ^= 1; }
        }
    }

    // ---- MMA issuer: thread 32 of each CTA (fully local cg1 MMAs) ----
    if (tid == 32) {
        int s = 0, phase = 0;
        for (int i = 0; i < KC; ++i) {
            mbar_wait(full0 + s * 8, phase);
            const uint32_t stg = sbase + SMEM_STAGE0 + s * STAGE_BYTES;
            uint64_t ad = make_desc(stg);
            uint64_t bd = make_desc(stg + BLK_BYTES);
#pragma unroll
            for (int ks = 0; ks < 4; ++ks) {
                mma_f16_ss(tmem_base, ad + ks * 2, bd + ks * 2, IDESC,
                           (i > 0 || ks > 0) ? 1u : 0u);
            }
            tc_commit_mc(empty0 + s * 8, 0x3);   // free stage on BOTH CTAs
            if (++s == STAGES) { s = 0; phase ^= 1; }
        }
        tc_commit(doneb);
    }

    // ---- epilogue: 8 warps; warp w = subpartition (w&3), col half (w>>2) ----
    mbar_wait(doneb, 0);
    tc_fence_after();

    const int subp    = wid & 3;
    const int colhalf = wid >> 2;
    const int row = mb * 128 + subp * 32 + lane;
    float* orow = Out + (size_t)row * N + nb2 * 256 + colhalf * 128;
    const float* brow = bias + nb2 * 256 + colhalf * 128;

#pragma unroll
    for (int cb = 0; cb < 4; ++cb) {
        uint32_t r32[32];
        ldtm_x32(r32, tmem_base + colhalf * 128 + cb * 32);
        tc_wait_ld();
        float o[32];
#pragma unroll
        for (int c = 0; c < 32; ++c) {
            __half h  = __float2half_rn(__uint_as_float(r32[c]));
            __half hb = __float2half_rn(__ldg(brow + cb * 32 + c));
            o[c] = __half2float(__hadd(h, hb));
        }
#pragma unroll
        for (int q = 0; q < 8; ++q) {
            reinterpret_cast<float4*>(orow + cb * 32)[q] =
                make_float4(o[4 * q], o[4 * q + 1], o[4 * q + 2], o[4 * q + 3]);
        }
    }

    __syncthreads();
    if (wid == 0) tmem_dealloc(tmem_base, 256);
    // peer may still be multicasting into this CTA's smem — hold until done
    CLUSTER_SYNC_();

#else
    // =============== compile-only fallback (never selected on GB300) =======
    if (tid < 128) {
        const int m = mb * 128 + tid;
        for (int c = 0; c < 256; ++c) {
            const int n = nb2 * 256 + c;
            float acc = 0.0f;
            for (int k = 0; k < K; ++k) {
                size_t ablk = (size_t)(m >> 7) * KC + (k >> 6);
                const __half* ae = reinterpret_cast<const __half*>(
                    reinterpret_cast<const char*>(g_X) + ablk * BLK_BYTES +
                    swz128((uint32_t)((m & 127) * 128 + (k & 63) * 2)));
                size_t bblk = ((size_t)(n >> 8) * KC + (k >> 6)) * 2 + ((n >> 7) & 1);
                const __half* be = reinterpret_cast<const __half*>(
                    reinterpret_cast<const char*>(g_W) + bblk * BLK_BYTES +
                    swz128((uint32_t)((n & 127) * 128 + (k & 63) * 2)));
                acc += __half2float(*ae) * __half2float(*be);
            }
            __half h = __hadd(__float2half_rn(acc), __float2half_rn(__ldg(bias + n)));
            Out[(size_t)m * N + n] = __half2float(h);
        }
    }
#endif
}

// ---------------------------------------------------------------------------
extern "C" void kernel_launch(void* const* d_in, const int* in_sizes, int n_in,
                              void* d_out, int out_size) {
    const float* x     = (const float*)d_in[0];
    const int*   wq    = (const int*)d_in[1];
    const float* scale = (const float*)d_in[2];
    const float* bias  = (const float*)d_in[3];
    float*       out   = (float*)d_out;

    const int O = in_sizes[3];                    // 4096
    const int K = (in_sizes[1] / O) * 2;          // 4096
    const int M = in_sizes[0] / K;                // 8192
    const int N = O;

    const int nbytes = in_sizes[1];
    dequant_kernel<<<(nbytes / 4 + 255) / 256, 256>>>(wq, scale, nbytes, K);

    const int nx = in_sizes[0];
    convert_x_kernel<<<(nx / 8 + 255) / 256, 256>>>(x, nx, K);

    cudaFuncSetAttribute(gemm_kernel,
                         cudaFuncAttributeMaxDynamicSharedMemorySize,
                         SMEM_TOTAL_GEMM);
    dim3 grid(M / 128, N / 256);
    gemm_kernel<<<grid, 256, SMEM_TOTAL_GEMM>>>(bias, out, M, N, K);
}

// round 8
// speedup vs baseline: 1.2001x; 1.1359x over previous
#include <cuda_runtime.h>
#include <cuda_fp16.h>
#include <cstdint>

// ============================================================================
// INT4Linear on GB300 — PERSISTENT warp-specialized tcgen05 cg1 GEMM.
//   out[M,N] = x[M,K] @ W[N,K]^T + bias     M=8192 N=4096 K=4096
// k1: dequant int4 -> g_W fp16, SW128 blocks [N/256][K/64][2][128x64]
// k2: x fp32 -> g_X fp16, SW128 blocks [M/128][K/64][128x64]
// k3: persistent GEMM: grid = #SMs, each CTA loops tiles t = bid + i*grid.
//     Warps 0-7: epilogue. Warp 8: TMA producer. Warp 9: MMA issuer.
//     TMEM 512 cols = 2 accumulator buffers (0/256): epilogue of tile j
//     overlaps mainloop of tile j+1 (R4 lost ~50us to 7x wave-boundary
//     prologue/epilogue/drain serialization; clusters regressed in R5/R7).
// ============================================================================

#if defined(__CUDA_ARCH_FEAT_SM103_ALL) || defined(__CUDA_ARCH_FEAT_SM100_ALL)
#define TC_PATH 1
#else
#define TC_PATH 0
#endif

#define KC_ELEMS 64
#define BLK_BYTES 16384
#define STAGES 4
#define STAGE_BYTES (3 * BLK_BYTES)   // A 16KB + B 32KB
#define SMEM_STAGE0 1024
#define SMEM_TOTAL_GEMM (SMEM_STAGE0 + STAGES * STAGE_BYTES)   // 197632
#define THREADS 320                   // 8 epi warps + producer warp + issuer warp

__device__ __half g_W[4096u * 4096u];   // 32 MB, tiled+swizzled
__device__ __half g_X[8192u * 4096u];   // 64 MB, tiled+swizzled

__host__ __device__ __forceinline__ uint32_t swz128(uint32_t o) {
    return o ^ ((o >> 3) & 0x70);
}
__device__ __forceinline__ uint32_t smem_u32(const void* p) {
    return (uint32_t)__cvta_generic_to_shared(p);
}

// ---------------------------------------------------------------------------
#if TC_PATH
__device__ __forceinline__ void mbar_init(uint32_t a, uint32_t cnt) {
    asm volatile("mbarrier.init.shared.b64 [%0], %1;" :: "r"(a), "r"(cnt) : "memory");
}
__device__ __forceinline__ void mbar_arrive(uint32_t a) {
    asm volatile("mbarrier.arrive.shared.b64 _, [%0];" :: "r"(a) : "memory");
}
__device__ __forceinline__ void mbar_expect_tx(uint32_t a, uint32_t bytes) {
    asm volatile("mbarrier.arrive.expect_tx.shared.b64 _, [%0], %1;"
                 :: "r"(a), "r"(bytes) : "memory");
}
__device__ __forceinline__ void mbar_wait(uint32_t a, uint32_t parity) {
    uint32_t done;
    asm volatile(
        "{\n\t.reg .pred p;\n\t"
        "mbarrier.try_wait.parity.acquire.cta.shared::cta.b64 p, [%1], %2;\n\t"
        "selp.b32 %0, 1, 0, p;\n\t}"
        : "=r"(done) : "r"(a), "r"(parity) : "memory");
    if (!done) {
        asm volatile(
            "{\n\t.reg .pred P1;\n\t"
            "W0_%=:\n\t"
            "mbarrier.try_wait.parity.acquire.cta.shared::cta.b64 P1, [%0], %1, 0x989680;\n\t"
            "@P1 bra.uni W1_%=;\n\t"
            "bra.uni W0_%=;\n\t"
            "W1_%=:\n\t}"
            :: "r"(a), "r"(parity) : "memory");
    }
}
__device__ __forceinline__ void bulk_g2s(uint32_t dst, const void* src,
                                         uint32_t bytes, uint32_t mbar) {
    asm volatile(
        "cp.async.bulk.shared::cluster.global.mbarrier::complete_tx::bytes "
        "[%0], [%1], %2, [%3];"
        :: "r"(dst), "l"(src), "r"(bytes), "r"(mbar) : "memory");
}
__device__ __forceinline__ void tmem_alloc(uint32_t smem_slot, uint32_t ncols) {
    asm volatile("tcgen05.alloc.cta_group::1.sync.aligned.shared::cta.b32 [%0], %1;"
                 :: "r"(smem_slot), "r"(ncols) : "memory");
}
__device__ __forceinline__ void tmem_relinquish() {
    asm volatile("tcgen05.relinquish_alloc_permit.cta_group::1.sync.aligned;");
}
__device__ __forceinline__ void tmem_dealloc(uint32_t base, uint32_t ncols) {
    asm volatile("tcgen05.dealloc.cta_group::1.sync.aligned.b32 %0, %1;"
                 :: "r"(base), "r"(ncols));
}
__device__ __forceinline__ void mma_f16_ss(uint32_t d_tmem, uint64_t a_desc,
                                           uint64_t b_desc, uint32_t idesc,
                                           uint32_t enable) {
    asm volatile(
        "{\n\t.reg .pred p;\n\t"
        "setp.ne.u32 p, %5, 0;\n\t"
        "tcgen05.mma.cta_group::1.kind::f16 [%0], %1, %2, %3, {%4, %4, %4, %4}, p;\n\t}"
        :: "r"(d_tmem), "l"(a_desc), "l"(b_desc), "r"(idesc), "r"(0u), "r"(enable)
        : "memory");
}
__device__ __forceinline__ void tc_commit(uint32_t mbar) {
    asm volatile(
        "tcgen05.commit.cta_group::1.mbarrier::arrive::one.shared::cluster.b64 [%0];"
        :: "r"(mbar) : "memory");
}
__device__ __forceinline__ void tc_fence_after() {
    asm volatile("tcgen05.fence::after_thread_sync;" ::: "memory");
}
__device__ __forceinline__ void tc_fence_before() {
    asm volatile("tcgen05.fence::before_thread_sync;" ::: "memory");
}
__device__ __forceinline__ void ldtm_x32(uint32_t* r, uint32_t addr) {
    asm volatile(
        "tcgen05.ld.sync.aligned.32x32b.x32.b32 "
        "{%0,%1,%2,%3,%4,%5,%6,%7,%8,%9,%10,%11,%12,%13,%14,%15,"
        "%16,%17,%18,%19,%20,%21,%22,%23,%24,%25,%26,%27,%28,%29,%30,%31}, [%32];"
        : "=r"(r[0]), "=r"(r[1]), "=r"(r[2]), "=r"(r[3]),
          "=r"(r[4]), "=r"(r[5]), "=r"(r[6]), "=r"(r[7]),
          "=r"(r[8]), "=r"(r[9]), "=r"(r[10]), "=r"(r[11]),
          "=r"(r[12]), "=r"(r[13]), "=r"(r[14]), "=r"(r[15]),
          "=r"(r[16]), "=r"(r[17]), "=r"(r[18]), "=r"(r[19]),
          "=r"(r[20]), "=r"(r[21]), "=r"(r[22]), "=r"(r[23]),
          "=r"(r[24]), "=r"(r[25]), "=r"(r[26]), "=r"(r[27]),
          "=r"(r[28]), "=r"(r[29]), "=r"(r[30]), "=r"(r[31])
        : "r"(addr));
}
__device__ __forceinline__ void tc_wait_ld() {
    asm volatile("tcgen05.wait::ld.sync.aligned;" ::: "memory");
}
// SW128 K-major SMEM descriptor (version=1, LBO=1, SBO=64)
__device__ __forceinline__ uint64_t make_desc(uint32_t smem_addr) {
    const uint64_t base =
        (uint64_t(2) << 61) | (uint64_t(1) << 46) | (uint64_t(64) << 32) | (uint64_t(1) << 16);
    return base | ((uint64_t)(smem_addr >> 4) & 0x3FFF);
}
// idesc cg1: dtype F32 (1<<4), fp16 a/b, N=256 (32<<17), M=128 (8<<24)
#define IDESC 0x8400010u
#endif  // TC_PATH

// ---------------------------------------------------------------------------
// k1: dequant int4 -> g_W blocks [N/256][K/64][2][16KB]
// ---------------------------------------------------------------------------
__global__ void dequant_kernel(const int* __restrict__ packed,
                               const float* __restrict__ scale_p,
                               int total_bytes, int K) {
    int t = blockIdx.x * blockDim.x + threadIdx.x;
    if (t * 4 >= total_bytes) return;
    const float s = __ldg(scale_p);
    const int K2 = K >> 1;
    const int KC = K / KC_ELEMS;
    const int4 v = reinterpret_cast<const int4*>(packed)[t];

    int n  = (t * 4) / K2;
    int k0 = ((t * 4) % K2) * 2;

    __half out[8];
    const int b[4] = {v.x, v.y, v.z, v.w};
#pragma unroll
    for (int j = 0; j < 4; ++j) {
        int hi = b[j] >> 4;
        int lo = ((b[j] & 15) ^ 8) - 8;
        out[2 * j]     = __float2half_rn((float)hi * s);
        out[2 * j + 1] = __float2half_rn((float)lo * s);
    }

    int n2   = n >> 8;
    int half = (n >> 7) & 1;
    int r    = n & 127;
    int kc   = k0 >> 6;
    int c    = k0 & 63;
    size_t blk = ((size_t)n2 * KC + kc) * 2 + half;
    size_t off = blk * BLK_BYTES + swz128((uint32_t)(r * 128 + c * 2));
    *reinterpret_cast<uint4*>(reinterpret_cast<char*>(g_W) + off) =
        *reinterpret_cast<const uint4*>(out);
}

// ---------------------------------------------------------------------------
// k2: x fp32 -> g_X blocks [M/128][K/64][16KB]
// ---------------------------------------------------------------------------
__global__ void convert_x_kernel(const float* __restrict__ x, int total, int K) {
    int t = blockIdx.x * blockDim.x + threadIdx.x;
    if (t * 8 >= total) return;
    const int KC = K / KC_ELEMS;
    float4 a = reinterpret_cast<const float4*>(x)[t * 2];
    float4 c4 = reinterpret_cast<const float4*>(x)[t * 2 + 1];
    __half out[8];
    out[0] = __float2half_rn(a.x);  out[1] = __float2half_rn(a.y);
    out[2] = __float2half_rn(a.z);  out[3] = __float2half_rn(a.w);
    out[4] = __float2half_rn(c4.x); out[5] = __float2half_rn(c4.y);
    out[6] = __float2half_rn(c4.z); out[7] = __float2half_rn(c4.w);

    int m  = (t * 8) / K;
    int k0 = (t * 8) % K;
    int mb = m >> 7;
    int r  = m & 127;
    int kc = k0 >> 6;
    int c  = k0 & 63;
    size_t blk = (size_t)mb * KC + kc;
    size_t off = blk * BLK_BYTES + swz128((uint32_t)(r * 128 + c * 2));
    *reinterpret_cast<uint4*>(reinterpret_cast<char*>(g_X) + off) =
        *reinterpret_cast<const uint4*>(out);
}

// ---------------------------------------------------------------------------
// k3: persistent GEMM. grid = #SMs. Tile t: mb = t % (M/128), nb = t / (M/128).
// smem: full[4]@0, empty[4]@32, done[2]@64, efree[2]@80, tslot@96,
//       stages @1024 (A 16KB | B 32KB each).
// ---------------------------------------------------------------------------
__global__ __launch_bounds__(THREADS, 1)
void gemm_kernel(const float* __restrict__ bias,
                 float* __restrict__ Out,
                 int M, int N, int K, int ntiles) {
    extern __shared__ char smem[];
    const uint32_t sbase = smem_u32(smem);
    const int tid  = threadIdx.x;
    const int wid  = tid >> 5;
    const int lane = tid & 31;

    const int KC      = K / KC_ELEMS;            // 64 chunks per tile
    const int TILES_M = M / 128;                 // 64

#if TC_PATH
    const uint32_t full0  = sbase;               // full[s]  : +0  + s*8
    const uint32_t empty0 = sbase + 32;          // empty[s] : +32 + s*8
    const uint32_t done0  = sbase + 64;          // done[b]  : +64 + b*8
    const uint32_t efree0 = sbase + 80;          // efree[b] : +80 + b*8
    const uint32_t tslot  = sbase + 96;

    if (tid == 0) {
#pragma unroll
        for (int s = 0; s < STAGES; ++s) {
            mbar_init(full0 + s * 8, 1);
            mbar_init(empty0 + s * 8, 1);
        }
        mbar_init(done0, 1);     mbar_init(done0 + 8, 1);
        mbar_init(efree0, 8);    mbar_init(efree0 + 8, 8);   // 8 epi warps
    }
    __syncthreads();

    if (wid == 8) {
        tmem_alloc(tslot, 512);                  // 2 x 256-col accumulators
        tmem_relinquish();
    }
    __syncthreads();
    uint32_t tmem_base;
    asm volatile("ld.shared.b32 %0, [%1];" : "=r"(tmem_base) : "r"(tslot));

    // ==================== producer: warp 8, lane 0 ====================
    if (tid == 256) {
        int s = 0, ph = 1;
        for (int t = blockIdx.x; t < ntiles; t += gridDim.x) {
            const int mb = t % TILES_M;
            const int nb = t / TILES_M;
            const char* Asrc = reinterpret_cast<const char*>(g_X) +
                               (size_t)mb * KC * BLK_BYTES;
            const char* Bsrc = reinterpret_cast<const char*>(g_W) +
                               (size_t)nb * KC * 2 * BLK_BYTES;
            for (int i = 0; i < KC; ++i) {
                mbar_wait(empty0 + s * 8, ph);
                const uint32_t fb = full0 + s * 8;
                mbar_expect_tx(fb, STAGE_BYTES);
                const uint32_t stg = sbase + SMEM_STAGE0 + s * STAGE_BYTES;
                bulk_g2s(stg,             Asrc + (size_t)i * BLK_BYTES,     BLK_BYTES,     fb);
                bulk_g2s(stg + BLK_BYTES, Bsrc + (size_t)i * 2 * BLK_BYTES, 2 * BLK_BYTES, fb);
                if (++s == STAGES) { s = 0; ph ^= 1; }
            }
        }
    }

    // ==================== MMA issuer: warp 9, lane 0 ====================
    if (tid == 288) {
        int s = 0, ph = 0;
        int j = 0;                               // local tile index
        for (int t = blockIdx.x; t < ntiles; t += gridDim.x, ++j) {
            const int buf = j & 1;
            const int u   = j >> 1;              // use count of this buffer
            if (u > 0) {                         // buffer must be drained
                mbar_wait(efree0 + buf * 8, (u - 1) & 1);
            }
            tc_fence_after();
            const uint32_t dacc = tmem_base + buf * 256;
            for (int i = 0; i < KC; ++i) {
                mbar_wait(full0 + s * 8, ph);
                const uint32_t stg = sbase + SMEM_STAGE0 + s * STAGE_BYTES;
                uint64_t ad = make_desc(stg);
                uint64_t bd = make_desc(stg + BLK_BYTES);
#pragma unroll
                for (int ks = 0; ks < 4; ++ks) {
                    mma_f16_ss(dacc, ad + ks * 2, bd + ks * 2, IDESC,
                               (i > 0 || ks > 0) ? 1u : 0u);
                }
                tc_commit(empty0 + s * 8);
                if (++s == STAGES) { s = 0; ph ^= 1; }
            }
            tc_commit(done0 + buf * 8);          // fires when tile's MMAs done
        }
    }

    // ==================== epilogue: warps 0-7 ====================
    if (wid < 8) {
        const int subp    = wid & 3;             // TMEM subpartition (rows)
        const int colhalf = wid >> 2;            // 0: cols 0-127, 1: 128-255
        int j = 0;
        for (int t = blockIdx.x; t < ntiles; t += gridDim.x, ++j) {
            const int buf = j & 1;
            const int u   = j >> 1;
            mbar_wait(done0 + buf * 8, u & 1);
            tc_fence_after();

            const int mb = t % TILES_M;
            const int nb = t / TILES_M;
            const int row = mb * 128 + subp * 32 + lane;
            float* orow = Out + (size_t)row * N + nb * 256 + colhalf * 128;
            const float* brow = bias + nb * 256 + colhalf * 128;
            const uint32_t tacc = tmem_base + buf * 256 + colhalf * 128;

#pragma unroll
            for (int cb = 0; cb < 4; ++cb) {
                uint32_t r32[32];
                ldtm_x32(r32, tacc + cb * 32);
                tc_wait_ld();
                float o[32];
#pragma unroll
                for (int c = 0; c < 32; ++c) {
                    __half h  = __float2half_rn(__uint_as_float(r32[c]));
                    __half hb = __float2half_rn(__ldg(brow + cb * 32 + c));
                    o[c] = __half2float(__hadd(h, hb));
                }
#pragma unroll
                for (int q = 0; q < 8; ++q) {
                    reinterpret_cast<float4*>(orow + cb * 32)[q] =
                        make_float4(o[4 * q], o[4 * q + 1], o[4 * q + 2], o[4 * q + 3]);
                }
            }
            tc_fence_before();
            if (lane == 0) mbar_arrive(efree0 + buf * 8);  // buffer drained
        }
    }

    __syncthreads();
    if (wid == 8) tmem_dealloc(tmem_base, 512);

#else
    // =============== compile-only fallback (never selected on GB300) =======
    for (int t = blockIdx.x; t < ntiles; t += gridDim.x) {
        const int mb = t % TILES_M;
        const int nb = t / TILES_M;
        if (tid < 128) {
            const int m = mb * 128 + tid;
            for (int c = 0; c < 256; ++c) {
                const int n = nb * 256 + c;
                float acc = 0.0f;
                for (int k = 0; k < K; ++k) {
                    size_t ablk = (size_t)(m >> 7) * KC + (k >> 6);
                    const __half* ae = reinterpret_cast<const __half*>(
                        reinterpret_cast<const char*>(g_X) + ablk * BLK_BYTES +
                        swz128((uint32_t)((m & 127) * 128 + (k & 63) * 2)));
                    size_t bblk = ((size_t)(n >> 8) * KC + (k >> 6)) * 2 + ((n >> 7) & 1);
                    const __half* be = reinterpret_cast<const __half*>(
                        reinterpret_cast<const char*>(g_W) + bblk * BLK_BYTES +
                        swz128((uint32_t)((n & 127) * 128 + (k & 63) * 2)));
                    acc += __half2float(*ae) * __half2float(*be);
                }
                __half h = __hadd(__float2half_rn(acc), __float2half_rn(__ldg(bias + n)));
                Out[(size_t)m * N + n] = __half2float(h);
            }
        }
    }
#endif
}

// ---------------------------------------------------------------------------
extern "C" void kernel_launch(void* const* d_in, const int* in_sizes, int n_in,
                              void* d_out, int out_size) {
    const float* x     = (const float*)d_in[0];
    const int*   wq    = (const int*)d_in[1];
    const float* scale = (const float*)d_in[2];
    const float* bias  = (const float*)d_in[3];
    float*       out   = (float*)d_out;

    const int O = in_sizes[3];                    // 4096
    const int K = (in_sizes[1] / O) * 2;          // 4096
    const int M = in_sizes[0] / K;                // 8192
    const int N = O;
    const int ntiles = (M / 128) * (N / 256);     // 1024

    const int nbytes = in_sizes[1];
    dequant_kernel<<<(nbytes / 4 + 255) / 256, 256>>>(wq, scale, nbytes, K);

    const int nx = in_sizes[0];
    convert_x_kernel<<<(nx / 8 + 255) / 256, 256>>>(x, nx, K);

    int nsm = 148;
    cudaDeviceGetAttribute(&nsm, cudaDevAttrMultiProcessorCount, 0);

    cudaFuncSetAttribute(gemm_kernel,
                         cudaFuncAttributeMaxDynamicSharedMemorySize,
                         SMEM_TOTAL_GEMM);
    gemm_kernel<<<nsm, THREADS, SMEM_TOTAL_GEMM>>>(bias, out, M, N, K, ntiles);
}